// round 2
// baseline (speedup 1.0000x reference)
#include <cuda_runtime.h>
#include <math.h>

#define CC 8192
#define DD 512
#define BM 128
#define BN 128
#define BK 16
#define TM 8
#define TN 8
#define NSPLIT 2
#define NT_PER_SPLIT ((CC / BN) / NSPLIT)   // 32

// ---- scratch (static __device__, no allocations) ----
__device__ float g_rnorm[CC];
__device__ float g_GT[DD * CC];             // 16 MB: GT[k][row] = G[row][k] (normalized)
__device__ float g_maxv[NSPLIT][CC];
__device__ int   g_am[NSPLIT][CC];
__device__ float g_minv[NSPLIT][CC];
__device__ int   g_an[NSPLIT][CC];
__device__ float g_esum[NSPLIT][CC];
__device__ float g_terms[CC];

// ------------------------------------------------------------------
// 1) per-row reciprocal L2 norm
// ------------------------------------------------------------------
__global__ void norms_kernel(const float* __restrict__ x) {
    int row = blockIdx.x;
    float4 v = ((const float4*)(x + row * DD))[threadIdx.x];   // 128 threads * 4 = 512
    float s = v.x * v.x + v.y * v.y + v.z * v.z + v.w * v.w;
    #pragma unroll
    for (int o = 16; o > 0; o >>= 1) s += __shfl_xor_sync(0xffffffffu, s, o);
    __shared__ float sh[4];
    int lane = threadIdx.x & 31, warp = threadIdx.x >> 5;
    if (lane == 0) sh[warp] = s;
    __syncthreads();
    if (threadIdx.x == 0)
        g_rnorm[row] = rsqrtf(sh[0] + sh[1] + sh[2] + sh[3]);
}

// ------------------------------------------------------------------
// 2) transpose + scale: GT[k][row] = x[row][k] * rnorm[row]
// ------------------------------------------------------------------
__global__ void transpose_kernel(const float* __restrict__ x) {
    __shared__ float tile[32][33];
    int kBase = blockIdx.x * 32;
    int rBase = blockIdx.y * 32;
    #pragma unroll
    for (int i = threadIdx.y; i < 32; i += 8) {
        int row = rBase + i;
        tile[i][threadIdx.x] = x[row * DD + kBase + threadIdx.x] * g_rnorm[row];
    }
    __syncthreads();
    #pragma unroll
    for (int i = threadIdx.y; i < 32; i += 8) {
        g_GT[(kBase + i) * CC + rBase + threadIdx.x] = tile[threadIdx.x][i];
    }
}

// ------------------------------------------------------------------
// 3) fused S = G G^T + per-row off-diag {max,argmax,min,argmin,sum exp}
//    grid = (CC/BM, NSPLIT); each block owns 128 rows, half the columns.
// ------------------------------------------------------------------
__global__ void __launch_bounds__(256) simstat_kernel() {
    __shared__ float As[BK][BM];
    __shared__ float Bs[BK][BN];

    const int rowBase = blockIdx.x * BM;
    const int split   = blockIdx.y;
    const int tid = threadIdx.x;
    const int tx = tid & 15;            // column group (TN=8 cols)
    const int ty = tid >> 4;            // row group    (TM=8 rows)

    float maxv[TM], minv[TM], esum[TM];
    int   am[TM], an[TM];
    #pragma unroll
    for (int i = 0; i < TM; i++) {
        maxv[i] = -2.0f; minv[i] = 2.0f; esum[i] = 0.0f; am[i] = 0; an[i] = 0;
    }

    for (int nt = 0; nt < NT_PER_SPLIT; nt++) {
        const int colBase = (split * NT_PER_SPLIT + nt) * BN;

        float acc[TM][TN];
        #pragma unroll
        for (int i = 0; i < TM; i++)
            #pragma unroll
            for (int j = 0; j < TN; j++) acc[i][j] = 0.0f;

        for (int k0 = 0; k0 < DD; k0 += BK) {
            // load tiles from GT (coalesced, conflict-free stores)
            #pragma unroll
            for (int v = 0; v < 2; v++) {
                int e    = tid + v * 256;        // 0..511
                int kk   = e >> 5;               // /32 float4 per k-row
                int seg4 = (e & 31) << 2;
                *(float4*)&As[kk][seg4] =
                    *(const float4*)&g_GT[(k0 + kk) * CC + rowBase + seg4];
                *(float4*)&Bs[kk][seg4] =
                    *(const float4*)&g_GT[(k0 + kk) * CC + colBase + seg4];
            }
            __syncthreads();

            #pragma unroll
            for (int kk = 0; kk < BK; kk++) {
                float a[TM], b[TN];
                float4 a0 = *(const float4*)&As[kk][ty * TM];
                float4 a1 = *(const float4*)&As[kk][ty * TM + 4];
                float4 b0 = *(const float4*)&Bs[kk][tx * TN];
                float4 b1 = *(const float4*)&Bs[kk][tx * TN + 4];
                a[0]=a0.x; a[1]=a0.y; a[2]=a0.z; a[3]=a0.w;
                a[4]=a1.x; a[5]=a1.y; a[6]=a1.z; a[7]=a1.w;
                b[0]=b0.x; b[1]=b0.y; b[2]=b0.z; b[3]=b0.w;
                b[4]=b1.x; b[5]=b1.y; b[6]=b1.z; b[7]=b1.w;
                #pragma unroll
                for (int i = 0; i < TM; i++)
                    #pragma unroll
                    for (int j = 0; j < TN; j++)
                        acc[i][j] = fmaf(a[i], b[j], acc[i][j]);
            }
            __syncthreads();
        }

        // epilogue: fold this 128x128 tile into the running row stats
        #pragma unroll
        for (int i = 0; i < TM; i++) {
            int grow = rowBase + ty * TM + i;
            #pragma unroll
            for (int j = 0; j < TN; j++) {
                int gcol = colBase + tx * TN + j;
                if (gcol != grow) {
                    float v = acc[i][j];
                    esum[i] += __expf(v);
                    if (v > maxv[i]) { maxv[i] = v; am[i] = gcol; }
                    if (v < minv[i]) { minv[i] = v; an[i] = gcol; }
                }
            }
        }
    }

    // combine across the 16 tx lanes (butterfly within 16-lane subgroups)
    #pragma unroll
    for (int i = 0; i < TM; i++) {
        #pragma unroll
        for (int o = 1; o < 16; o <<= 1) {
            float vm = __shfl_xor_sync(0xffffffffu, maxv[i], o);
            int   im = __shfl_xor_sync(0xffffffffu, am[i],  o);
            if (vm > maxv[i] || (vm == maxv[i] && im < am[i])) { maxv[i] = vm; am[i] = im; }
            float vn = __shfl_xor_sync(0xffffffffu, minv[i], o);
            int   jn = __shfl_xor_sync(0xffffffffu, an[i],  o);
            if (vn < minv[i] || (vn == minv[i] && jn < an[i])) { minv[i] = vn; an[i] = jn; }
            esum[i] += __shfl_xor_sync(0xffffffffu, esum[i], o);
        }
    }
    if (tx == 0) {
        #pragma unroll
        for (int i = 0; i < TM; i++) {
            int grow = rowBase + ty * TM + i;
            g_maxv[split][grow] = maxv[i];
            g_am[split][grow]   = am[i];
            g_minv[split][grow] = minv[i];
            g_an[split][grow]   = an[i];
            g_esum[split][grow] = esum[i];
        }
    }
}

// ------------------------------------------------------------------
// 4) combine splits, margin, w-distances, per-row loss term
// ------------------------------------------------------------------
__global__ void finalize_kernel(const float* __restrict__ w) {
    const int row = blockIdx.x;
    float m = -2.0f, mn = 2.0f, E = 0.0f;
    int ms = 0, ls = 0;
    #pragma unroll
    for (int s = 0; s < NSPLIT; s++) {
        float v = g_maxv[s][row]; int iv = g_am[s][row];
        if (v > m || (v == m && iv < ms)) { m = v; ms = iv; }
        float u = g_minv[s][row]; int ju = g_an[s][row];
        if (u < mn || (u == mn && ju < ls)) { mn = u; ls = ju; }
        E += g_esum[s][row];
    }
    float margin = (1.0f - expf(mn - m)) * expf(m) / E;

    int t = threadIdx.x;                           // 128 threads * float4 = 512
    float4 a = *(const float4*)&w[row * DD + t * 4];
    float4 b = *(const float4*)&w[ms  * DD + t * 4];
    float4 c = *(const float4*)&w[ls  * DD + t * 4];
    float dm = (a.x-b.x)*(a.x-b.x) + (a.y-b.y)*(a.y-b.y)
             + (a.z-b.z)*(a.z-b.z) + (a.w-b.w)*(a.w-b.w);
    float dl = (a.x-c.x)*(a.x-c.x) + (a.y-c.y)*(a.y-c.y)
             + (a.z-c.z)*(a.z-c.z) + (a.w-c.w)*(a.w-c.w);
    #pragma unroll
    for (int o = 16; o > 0; o >>= 1) {
        dm += __shfl_xor_sync(0xffffffffu, dm, o);
        dl += __shfl_xor_sync(0xffffffffu, dl, o);
    }
    __shared__ float sdm[4], sdl[4];
    int lane = t & 31, warp = t >> 5;
    if (lane == 0) { sdm[warp] = dm; sdl[warp] = dl; }
    __syncthreads();
    if (t == 0) {
        float DM = sdm[0] + sdm[1] + sdm[2] + sdm[3];
        float DL = sdl[0] + sdl[1] + sdl[2] + sdl[3];
        g_terms[row] = fmaxf(0.0f, sqrtf(DM) - sqrtf(DL) + margin);
    }
}

// ------------------------------------------------------------------
// 5) deterministic mean
// ------------------------------------------------------------------
__global__ void reduce_kernel(float* __restrict__ out) {
    __shared__ float sh[256];
    int t = threadIdx.x;
    float s = 0.0f;
    for (int i = t; i < CC; i += 256) s += g_terms[i];
    sh[t] = s;
    __syncthreads();
    for (int o = 128; o > 0; o >>= 1) {
        if (t < o) sh[t] += sh[t + o];
        __syncthreads();
    }
    if (t == 0) out[0] = sh[0] / (float)CC;
}

// ------------------------------------------------------------------
extern "C" void kernel_launch(void* const* d_in, const int* in_sizes, int n_in,
                              void* d_out, int out_size) {
    (void)in_sizes; (void)n_in; (void)out_size;
    const float* gt = (const float*)d_in[0];
    const float* w  = (const float*)d_in[1];
    float* out = (float*)d_out;

    norms_kernel<<<CC, 128>>>(gt);
    transpose_kernel<<<dim3(DD / 32, CC / 32), dim3(32, 8)>>>(gt);
    simstat_kernel<<<dim3(CC / BM, NSPLIT), 256>>>();
    finalize_kernel<<<CC, 128>>>(w);
    reduce_kernel<<<1, 256>>>(out);
}